// round 17
// baseline (speedup 1.0000x reference)
#include <cuda_runtime.h>
#include <cuda_bf16.h>
#include <cuda_fp16.h>
#include <math.h>
#include <stdint.h>

// ---------------- problem constants ----------------
#define Bsz 4
#define Lsz 2048
#define Hsz 2048
#define Dsz 4096
#define Nst 16
#define Rsz 128
#define Msz (Bsz * Lsz)          // 8192
#define DBLW (Rsz + 2 * Nst)     // 160

// ---------------- scratch (device globals; no allocation) ----------------
__device__ __half g_xn_h [(size_t)Msz * Hsz];        // rmsnorm out
__device__ __half g_wip_h[(size_t)(2*Dsz) * Hsz];    // in_proj w
__device__ __half g_xz_h [(size_t)Msz * 2 * Dsz];    // in_proj out (xs | z)
__device__ __half g_xc_h [(size_t)Msz * Dsz];        // conv+silu out
__device__ __half g_xpw_h[(size_t)DBLW * Dsz];       // x_proj w
__device__ float  g_dbl  [(size_t)Msz * DBLW];       // x_proj out (B/C in fp32)
__device__ __half g_dti_h[(size_t)Msz * Rsz];        // dt_in
__device__ __half g_dtw_h[(size_t)Dsz * Rsz];        // dt_proj w
__device__ __half g_dt_h [(size_t)Msz * Dsz];        // softplus(dt)
__device__ __half g_y_h  [(size_t)Msz * Dsz];        // scan out
__device__ __half g_opw_h[(size_t)Hsz * Dsz];        // out_proj w

// ---------------- helpers ----------------
__device__ __forceinline__ uint32_t smem_to_u32(const void* p) {
    uint32_t a;
    asm("{ .reg .u64 t; cvta.to.shared.u64 t, %1; cvt.u32.u64 %0, t; }" : "=r"(a) : "l"(p));
    return a;
}
__device__ __forceinline__ void ldsm4(uint32_t& r0, uint32_t& r1, uint32_t& r2, uint32_t& r3, uint32_t a) {
    asm volatile("ldmatrix.sync.aligned.m8n8.x4.shared.b16 {%0,%1,%2,%3}, [%4];"
                 : "=r"(r0), "=r"(r1), "=r"(r2), "=r"(r3) : "r"(a));
}
__device__ __forceinline__ void mma_fp16(float* c, const uint32_t* a, uint32_t b0, uint32_t b1) {
    asm volatile("mma.sync.aligned.m16n8k16.row.col.f32.f16.f16.f32 "
                 "{%0,%1,%2,%3}, {%4,%5,%6,%7}, {%8,%9}, {%0,%1,%2,%3};"
                 : "+f"(c[0]), "+f"(c[1]), "+f"(c[2]), "+f"(c[3])
                 : "r"(a[0]), "r"(a[1]), "r"(a[2]), "r"(a[3]), "r"(b0), "r"(b1));
}
__device__ __forceinline__ void cp16(uint32_t dst, const void* src) {
    asm volatile("cp.async.cg.shared.global [%0], [%1], 16;" :: "r"(dst), "l"(src));
}
__device__ __forceinline__ void cp_commit() { asm volatile("cp.async.commit_group;" ::: "memory"); }
template <int N> __device__ __forceinline__ void cp_wait() {
    asm volatile("cp.async.wait_group %0;" :: "n"(N) : "memory");
}
__device__ __forceinline__ float softplus_f(float v) {
    return (v > 0.f) ? v + __logf(1.f + __expf(-v)) : __logf(1.f + __expf(v));
}

#define ROWB 80                      // bytes per smem row (32 elts + pad)
#define TILEB (128 * ROWB)           // 10240 bytes per 128-row operand tile
#define STAGE1 (2 * TILEB)           // stage: A + B

// ---------------- fp16 single-pass GEMM, cp.async double-buffered smem ----------------
// OutT in {float, __half}. epi: 0 = plain; 1 = softplus(acc+bias[n]); 2 = plain + fp16 dt_in (cols<Rsz)
template <typename OutT>
__global__ void __launch_bounds__(256, 2)
gemm1_kernel(const __half* __restrict__ A, const __half* __restrict__ B,
             const float* __restrict__ bias, OutT* __restrict__ C,
             __half* __restrict__ E16,
             int N, int K, int lda, int ldb, int ldc, int epi)
{
    __shared__ __align__(16) char smem[2 * STAGE1];   // 40 KB static
    uint32_t sb = smem_to_u32(smem);
    int t = threadIdx.x, wid = t >> 5, lane = t & 31;
    int m0 = blockIdx.y * 128, n0 = blockIdx.x * 128;
    int wm = wid >> 2, wn = wid & 3;

    float acc[4][4][4];
    #pragma unroll
    for (int i = 0; i < 4; i++)
        #pragma unroll
        for (int j = 0; j < 4; j++)
            #pragma unroll
            for (int v = 0; v < 4; v++) acc[i][j][v] = 0.f;

    uint32_t a_off = (uint32_t)((wm * 64 + (lane & 15)) * ROWB + ((lane >> 4) * 8) * 2);
    uint32_t b_off = (uint32_t)((wn * 32 + ((lane >> 4) & 1) * 8 + (lane & 7)) * ROWB
                                + (((lane >> 3) & 1) * 8) * 2);

    const __half* srcb[4];
    uint32_t      dsto[4];
    #pragma unroll
    for (int i = 0; i < 4; i++) {
        int cid = t + i * 256;
        int tile = cid >> 9;
        int idx  = cid & 511;
        int row  = idx >> 2;
        int ch   = idx & 3;
        dsto[i] = (uint32_t)(tile * TILEB + row * ROWB + ch * 16);
        if (tile == 0) srcb[i] = A + (size_t)(m0 + row) * lda + ch * 8;
        else {
            int n  = n0 + row;
            int cr = (n < N) ? n : 0;
            srcb[i] = B + (size_t)cr * ldb + ch * 8;
        }
    }

    const int KT = K / 32;
    // prologue: stage 0 via cp.async
    #pragma unroll
    for (int i = 0; i < 4; i++) cp16(sb + dsto[i], srcb[i]);
    cp_commit();

    for (int it = 0; it < KT; it++) {
        int s = it & 1;
        uint32_t stage = sb + s * STAGE1;
        // issue next stage loads (buffer free: compute on it-1 finished at end-of-iter barrier)
        if (it + 1 < KT) {
            int k0 = (it + 1) * 32;
            uint32_t dstbase = sb + (s ^ 1) * STAGE1;
            #pragma unroll
            for (int i = 0; i < 4; i++) cp16(dstbase + dsto[i], srcb[i] + k0);
            cp_commit();
            cp_wait<1>();                 // stage s complete (older group)
        } else {
            cp_wait<0>();
        }
        __syncthreads();                  // all threads' stage-s data visible

        #pragma unroll
        for (int ks = 0; ks < 2; ks++) {
            uint32_t bfr[8];
            uint32_t bbase = stage + TILEB + b_off + ks * 32;
            ldsm4(bfr[0], bfr[1], bfr[2], bfr[3], bbase);
            ldsm4(bfr[4], bfr[5], bfr[6], bfr[7], bbase + 16 * ROWB);
            uint32_t af[4][4];
            #pragma unroll
            for (int mi = 0; mi < 4; mi++)
                ldsm4(af[mi][0], af[mi][1], af[mi][2], af[mi][3],
                      stage + a_off + mi * 16 * ROWB + ks * 32);
            #pragma unroll
            for (int mi = 0; mi < 4; mi++)
                #pragma unroll
                for (int j = 0; j < 4; j++)
                    mma_fp16(acc[mi][j], af[mi], bfr[j*2], bfr[j*2+1]);
        }
        __syncthreads();                  // compute done before next iter overwrites stage s
    }

    #pragma unroll
    for (int mi = 0; mi < 4; mi++) {
        int row = m0 + wm * 64 + mi * 16 + (lane >> 2);
        #pragma unroll
        for (int j = 0; j < 4; j++) {
            int col = n0 + wn * 32 + j * 8 + (lane & 3) * 2;
            if (col < N) {
                float v0 = acc[mi][j][0], v1 = acc[mi][j][1];
                float v2 = acc[mi][j][2], v3 = acc[mi][j][3];
                if (epi == 1) {
                    float b0 = bias[col], b1 = bias[col + 1];
                    v0 = softplus_f(v0 + b0); v1 = softplus_f(v1 + b1);
                    v2 = softplus_f(v2 + b0); v3 = softplus_f(v3 + b1);
                }
                if constexpr (sizeof(OutT) == 4) {
                    *(float2*)((float*)C + (size_t)row * ldc + col)       = make_float2(v0, v1);
                    *(float2*)((float*)C + (size_t)(row + 8) * ldc + col) = make_float2(v2, v3);
                } else {
                    *(__half2*)((__half*)C + (size_t)row * ldc + col)       = __floats2half2_rn(v0, v1);
                    *(__half2*)((__half*)C + (size_t)(row + 8) * ldc + col) = __floats2half2_rn(v2, v3);
                }
                if (epi == 2 && col < Rsz) {
                    *(__half2*)(E16 + (size_t)row * Rsz + col)       = __floats2half2_rn(v0, v1);
                    *(__half2*)(E16 + (size_t)(row + 8) * Rsz + col) = __floats2half2_rn(v2, v3);
                }
            }
        }
    }
}

// ---------------- 1) x = h + r ; residual_out = x ; xn(fp16) = rmsnorm(x) ----------------
__global__ __launch_bounds__(256) void add_rmsnorm_kernel(
    const float* __restrict__ h, const float* __restrict__ r,
    const float* __restrict__ w, float* __restrict__ resid_out,
    __half* __restrict__ xh)
{
    int row = blockIdx.x;
    const float4* hp = (const float4*)(h + (size_t)row * Hsz);
    const float4* rp = (const float4*)(r + (size_t)row * Hsz);
    float4*       ro = (float4*)(resid_out + (size_t)row * Hsz);
    const float4* wp = (const float4*)w;
    int t = threadIdx.x;

    float4 v0, v1;
    { float4 a = hp[t], b = rp[t];
      v0 = make_float4(a.x+b.x, a.y+b.y, a.z+b.z, a.w+b.w);
      a = hp[t+256]; b = rp[t+256];
      v1 = make_float4(a.x+b.x, a.y+b.y, a.z+b.z, a.w+b.w); }
    float s = v0.x*v0.x+v0.y*v0.y+v0.z*v0.z+v0.w*v0.w
            + v1.x*v1.x+v1.y*v1.y+v1.z*v1.z+v1.w*v1.w;
    __shared__ float red[8];
    #pragma unroll
    for (int o = 16; o > 0; o >>= 1) s += __shfl_xor_sync(0xffffffffu, s, o);
    if ((t & 31) == 0) red[t >> 5] = s;
    __syncthreads();
    if (t == 0) { float tot = 0.f; for (int i = 0; i < 8; i++) tot += red[i]; red[0] = tot; }
    __syncthreads();
    float inv = rsqrtf(red[0] * (1.0f / Hsz) + 1e-5f);

    ro[t] = v0; ro[t + 256] = v1;
    float4 w0 = wp[t], w1 = wp[t + 256];
    float o0[8] = {v0.x*inv*w0.x, v0.y*inv*w0.y, v0.z*inv*w0.z, v0.w*inv*w0.w,
                   v1.x*inv*w1.x, v1.y*inv*w1.y, v1.z*inv*w1.z, v1.w*inv*w1.w};
    size_t base = (size_t)row * Hsz;
    #pragma unroll
    for (int j = 0; j < 4; j++) xh[base + t*4 + j]        = __float2half(o0[j]);
    #pragma unroll
    for (int j = 0; j < 4; j++) xh[base + 1024 + t*4 + j] = __float2half(o0[4 + j]);
}

// ---------------- f32 -> fp16 ----------------
__global__ __launch_bounds__(256) void cvt_f2h_kernel(
    const float* __restrict__ s, __half* __restrict__ d, size_t n)
{
    size_t i = (size_t)blockIdx.x * 256 + threadIdx.x;
    size_t stride = (size_t)gridDim.x * 256;
    for (; i < n; i += stride) d[i] = __float2half(s[i]);
}

// ---------------- 3) causal depthwise conv (K=4) + silu -> xc fp16 ----------------
#define CONV_CHUNK 256
__global__ __launch_bounds__(256) void conv_silu_kernel(
    const __half* __restrict__ xz, const float* __restrict__ cw,
    const float* __restrict__ cb, __half* __restrict__ xc)
{
    int d  = blockIdx.x * 256 + threadIdx.x;
    int l0 = blockIdx.y * CONV_CHUNK;
    int b  = blockIdx.z;
    size_t base = (size_t)b * Lsz;

    float w0 = cw[d*4+0], w1 = cw[d*4+1], w2 = cw[d*4+2], w3 = cw[d*4+3];
    float bias = cb[d];
    float xm3 = (l0 >= 3) ? __half2float(xz[(base + l0 - 3) * (2*Dsz) + d]) : 0.f;
    float xm2 = (l0 >= 2) ? __half2float(xz[(base + l0 - 2) * (2*Dsz) + d]) : 0.f;
    float xm1 = (l0 >= 1) ? __half2float(xz[(base + l0 - 1) * (2*Dsz) + d]) : 0.f;

    #pragma unroll 4
    for (int l = l0; l < l0 + CONV_CHUNK; l++) {
        float x0 = __half2float(xz[(base + l) * (2*Dsz) + d]);
        float v  = fmaf(w0, xm3, fmaf(w1, xm2, fmaf(w2, xm1, fmaf(w3, x0, bias))));
        float sv = v / (1.f + __expf(-v));
        xc[(base + l) * Dsz + d] = __float2half(sv);
        xm3 = xm2; xm2 = xm1; xm1 = x0;
    }
}

// ---------------- 5) selective scan: 4 lanes per (b,d), software-pipelined loads ----------------
__global__ __launch_bounds__(128) void scan4_kernel(
    const __half* __restrict__ dt, const __half* __restrict__ xc,
    const float* __restrict__ dbl, const __half* __restrict__ xz,
    const float* __restrict__ A_log, const float* __restrict__ D_param,
    __half* __restrict__ y)
{
    int gid = blockIdx.x * 128 + threadIdx.x;
    int sub = gid & 3;
    int pr  = gid >> 2;
    int d = pr & (Dsz - 1);
    int b = pr >> 12;

    float A[4], h[4];
    #pragma unroll
    for (int j = 0; j < 4; j++) {
        A[j] = -expf(A_log[d * Nst + sub * 4 + j]);
        h[j] = 0.f;
    }
    float Dp = D_param[d];
    size_t rb = (size_t)b * Lsz;

    float dtv = __half2float(dt[rb * Dsz + d]);
    float xv  = __half2float(xc[rb * Dsz + d]);
    float zv  = __half2float(xz[rb * (2*Dsz) + Dsz + d]);
    float4 Bv = *(const float4*)(dbl + rb * DBLW + Rsz + sub * 4);
    float4 Cv = *(const float4*)(dbl + rb * DBLW + Rsz + Nst + sub * 4);

    for (int l = 0; l < Lsz; l++) {
        int ln = (l + 1 < Lsz) ? (l + 1) : l;
        size_t r2 = rb + ln;
        float  p_dtv = __half2float(dt[r2 * Dsz + d]);
        float  p_xv  = __half2float(xc[r2 * Dsz + d]);
        float  p_zv  = __half2float(xz[r2 * (2*Dsz) + Dsz + d]);
        float4 p_Bv  = *(const float4*)(dbl + r2 * DBLW + Rsz + sub * 4);
        float4 p_Cv  = *(const float4*)(dbl + r2 * DBLW + Rsz + Nst + sub * 4);

        float dtx = dtv * xv;
        float ys = 0.f;
        h[0] = fmaf(__expf(dtv * A[0]), h[0], dtx * Bv.x); ys = fmaf(h[0], Cv.x, ys);
        h[1] = fmaf(__expf(dtv * A[1]), h[1], dtx * Bv.y); ys = fmaf(h[1], Cv.y, ys);
        h[2] = fmaf(__expf(dtv * A[2]), h[2], dtx * Bv.z); ys = fmaf(h[2], Cv.z, ys);
        h[3] = fmaf(__expf(dtv * A[3]), h[3], dtx * Bv.w); ys = fmaf(h[3], Cv.w, ys);
        ys += __shfl_xor_sync(0xffffffffu, ys, 1);
        ys += __shfl_xor_sync(0xffffffffu, ys, 2);

        if (sub == 0) {
            float yv = fmaf(xv, Dp, ys);
            float sg = zv / (1.f + __expf(-zv));
            y[(rb + l) * Dsz + d] = __float2half(yv * sg);
        }
        dtv = p_dtv; xv = p_xv; zv = p_zv; Bv = p_Bv; Cv = p_Cv;
    }
}

// ---------------- launcher ----------------
extern "C" void kernel_launch(void* const* d_in, const int* in_sizes, int n_in,
                              void* d_out, int out_size)
{
    const float* hidden    = (const float*)d_in[0];
    const float* residual  = (const float*)d_in[1];
    const float* norm_w    = (const float*)d_in[2];
    const float* in_proj_w = (const float*)d_in[3];
    const float* conv_w    = (const float*)d_in[4];
    const float* conv_b    = (const float*)d_in[5];
    const float* x_proj_w  = (const float*)d_in[6];
    const float* dt_proj_w = (const float*)d_in[7];
    const float* dt_proj_b = (const float*)d_in[8];
    const float* A_log     = (const float*)d_in[9];
    const float* D_param   = (const float*)d_in[10];
    const float* out_proj_w= (const float*)d_in[11];

    float* out       = (float*)d_out;
    float* resid_out = out + (size_t)Msz * Hsz;

    __half *xnh, *wih, *xzh, *xch, *xpw, *dih, *dwh, *dth, *yh, *owh;
    float *dbl;
    cudaGetSymbolAddress((void**)&xnh, g_xn_h);
    cudaGetSymbolAddress((void**)&wih, g_wip_h);
    cudaGetSymbolAddress((void**)&xzh, g_xz_h);
    cudaGetSymbolAddress((void**)&xch, g_xc_h);
    cudaGetSymbolAddress((void**)&xpw, g_xpw_h);
    cudaGetSymbolAddress((void**)&dbl, g_dbl);
    cudaGetSymbolAddress((void**)&dih, g_dti_h);
    cudaGetSymbolAddress((void**)&dwh, g_dtw_h);
    cudaGetSymbolAddress((void**)&dth, g_dt_h);
    cudaGetSymbolAddress((void**)&yh,  g_y_h);
    cudaGetSymbolAddress((void**)&owh, g_opw_h);

    // 1) rmsnorm (+ residual passthrough) -> xn fp16
    add_rmsnorm_kernel<<<Msz, 256>>>(hidden, residual, norm_w, resid_out, xnh);
    // 2-3) weight conversions needed by launch 4
    cvt_f2h_kernel<<<2048, 256>>>(in_proj_w,  wih, (size_t)(2*Dsz) * Hsz);
    cvt_f2h_kernel<<<1024, 256>>>(out_proj_w, owh, (size_t)Hsz * Dsz);

    // 4) in_proj: (8192 x 8192, K=2048) -> xz fp16   [ncu capture slot]
    {
        dim3 grid(2*Dsz / 128, Msz / 128);
        gemm1_kernel<__half><<<grid, 256>>>(xnh, wih, nullptr, xzh, nullptr,
                                            2*Dsz, Hsz, Hsz, Hsz, 2*Dsz, 0);
    }

    // 5-6) remaining weight conversions
    cvt_f2h_kernel<<<1024, 256>>>(x_proj_w,  xpw, (size_t)DBLW * Dsz);
    cvt_f2h_kernel<<<1024, 256>>>(dt_proj_w, dwh, (size_t)Dsz * Rsz);

    // 7) conv + silu -> xc fp16
    {
        dim3 grid(Dsz/256, Lsz/CONV_CHUNK, Bsz);
        conv_silu_kernel<<<grid, 256>>>(xzh, conv_w, conv_b, xch);
    }

    // 8) x_proj: (8192 x 160, K=4096) -> dbl fp32 (+ dt_in fp16 for cols<128)
    {
        dim3 grid(2, Msz / 128);
        gemm1_kernel<float><<<grid, 256>>>(xch, xpw, nullptr, dbl, dih,
                                           DBLW, Dsz, Dsz, Dsz, DBLW, 2);
    }

    // 9) dt: (8192 x 4096, K=128) + softplus -> dt fp16
    {
        dim3 grid(Dsz / 128, Msz / 128);
        gemm1_kernel<__half><<<grid, 256>>>(dih, dwh, dt_proj_b, dth, nullptr,
                                            Dsz, Rsz, Rsz, Rsz, Dsz, 1);
    }

    // 10) selective scan + gating -> y fp16
    scan4_kernel<<<(Bsz * Dsz * 4)/128, 128>>>(dth, xch, dbl, xzh, A_log, D_param, yh);

    // 11) out_proj: (8192 x 2048, K=4096) -> out fp32
    {
        dim3 grid(Hsz / 128, Msz / 128);
        gemm1_kernel<float><<<grid, 256>>>(yh, owh, nullptr, out, nullptr,
                                           Hsz, Dsz, Dsz, Dsz, Hsz, 0);
    }
    (void)in_sizes; (void)n_in; (void)out_size;
}